// round 17
// baseline (speedup 1.0000x reference)
#include <cuda_runtime.h>
#include <cuda_bf16.h>
#include <cstdint>

// Problem constants
#define NIMG 8
#define NGT  256
#define NPR  8000
#define BATCH 512
#define NPOSMAX 128
#define NBUCKET 1024
#define BCAP 64              // max records per bucket (mean: bg ~7, fg ~0.8)
#define FG_CAP 192           // >= NPOSMAX + BCAP
#define BG_CAP 576           // >= BATCH + BCAP
#define MBLK_PER_IMG 125     // match blocks per image (125 x 64 = 8000)

// Dynamic SMEM union layout (bytes)
#define SM_SKEY   0          // u64[BG_CAP]      = 4608
#define SM_GIDX   4608       // int[BG_CAP]      = 2304
#define SM_CUME   6912       // int[NBUCKET+1]   = 4100
#define SM_MAP    11012      // int[BATCH]       = 2048
#define SM_WSUM   13060      // int[8]           = 32
#define SM_MISC   13092      // int[2]
#define DSMEM_SZ  13120
// match view: sgt float4[256] @0 (4096), sag float[256] @4096, sgc int[256] @5120

// ---------------------------------------------------------------------------
// Threefry-2x32 (JAX default PRNG), 20 rounds.
// ---------------------------------------------------------------------------
__host__ __device__ __forceinline__ void threefry2x32(
    uint32_t k0, uint32_t k1, uint32_t x0, uint32_t x1,
    uint32_t& o0, uint32_t& o1)
{
    uint32_t ks0 = k0, ks1 = k1, ks2 = k0 ^ k1 ^ 0x1BD11BDAu;
    uint32_t a = x0 + ks0, b = x1 + ks1;
    const uint32_t rot[2][4] = {{13u,15u,26u,6u},{17u,29u,16u,24u}};
#pragma unroll
    for (int i = 0; i < 5; ++i) {
        const uint32_t* r = rot[i & 1];
#pragma unroll
        for (int q = 0; q < 4; ++q) {
            a += b;
            b = (b << r[q]) | (b >> (32u - r[q]));
            b ^= a;
        }
        uint32_t i1 = (uint32_t)(i + 1);
        uint32_t kA = (i % 3 == 0) ? ks1 : (i % 3 == 1) ? ks2 : ks0;
        uint32_t kB = (i % 3 == 0) ? ks2 : (i % 3 == 1) ? ks0 : ks1;
        a += kA;
        b += kB + i1;
    }
    o0 = a; o1 = b;
}

__host__ __device__ __forceinline__ float jax_uniform_from_bits(uint32_t bits) {
    uint32_t fb = (bits >> 9) | 0x3f800000u;
    float f;
#ifdef __CUDA_ARCH__
    f = __uint_as_float(fb);
#else
    union { uint32_t u; float f; } c; c.u = fb; f = c.f;
#endif
    return f - 1.0f;
}

struct ImgKeys {
    uint32_t v[NIMG][4];   // per image: k1 (2 words), k2 (2 words)
};

// ---------------------------------------------------------------------------
// Scratch (device globals — no allocation allowed).
// g_hist / g_done are all-zeros at module load; the select blocks restore
// them to zero every call, so every graph replay sees identical state.
// g_brec slots are gated by g_hist counts, so they need no clearing.
// Record layout (3 x float4 = 48B):
//   [0] = (u, bits(r), p.x, p.y)   [1] = (p.z, p.w, g.x, g.y)
//   [2] = (g.z, g.w, label_f, 0)
// ---------------------------------------------------------------------------
__device__ int    g_hist[NIMG * 2 * NBUCKET];
__device__ float4 g_brec[(size_t)NIMG * 2 * NBUCKET * BCAP * 3];
__device__ int    g_done[NIMG];

// ---------------------------------------------------------------------------
// Select role: one block per image, 256 threads. Spins until all 125 match
// blocks of its image have released their ticket, then performs the exact
// stable-argsort-prefix selection for fg (target 128) and bg (target 512)
// sequentially, writing the output rows directly from the bucketed records.
//   rank = cumE[bucket] + #(same-bucket keys < k); keys are unique u64
//   (score,index) -> total order -> rank bijection, independent of the
//   nondeterministic within-bucket atomic order.
// ---------------------------------------------------------------------------
__device__ __forceinline__ void select_role(int img, float* __restrict__ out,
                                            char* sm)
{
    unsigned long long* skey = (unsigned long long*)(sm + SM_SKEY);
    int* gidx = (int*)(sm + SM_GIDX);
    int* cumE = (int*)(sm + SM_CUME);
    int* map  = (int*)(sm + SM_MAP);
    int* wsum = (int*)(sm + SM_WSUM);
    int* misc = (int*)(sm + SM_MISC);   // [0] = threshold bucket

    const int tid  = threadIdx.x;
    const int lane = tid & 31;
    const int wrp  = tid >> 5;

    // Wait for all match blocks of this image (release via fence+atomic there)
    if (tid == 0) {
        while (atomicAdd(&g_done[img], 0) < MBLK_PER_IMG) __nanosleep(64);
    }
    __syncthreads();
    __threadfence();

    int np = 0;
    for (int pool = 0; pool < 2; ++pool) {
        const int target = pool ? BATCH : NPOSMAX;
        const int cap    = pool ? BG_CAP : FG_CAP;
        int* hist = &g_hist[(img * 2 + pool) * NBUCKET];
        const float4* bsrc =
            &g_brec[(size_t)(img * 2 + pool) * NBUCKET * BCAP * 3];

        if (tid == 0) misc[0] = NBUCKET - 1;
        __syncthreads();   // also guards smem reuse across pools

        // histogram load (4 buckets/thread) + reset for replay
        int4 h = reinterpret_cast<int4*>(hist)[tid];
        reinterpret_cast<int4*>(hist)[tid] = make_int4(0, 0, 0, 0);
        int v = h.x + h.y + h.z + h.w;
#pragma unroll
        for (int off = 1; off < 32; off <<= 1) {
            int o = __shfl_up_sync(0xffffffffu, v, off);
            if (lane >= off) v += o;
        }
        if (lane == 31) wsum[wrp] = v;
        __syncthreads();
        if (tid < 8) {
            int w = wsum[tid];
#pragma unroll
            for (int off = 1; off < 8; off <<= 1) {
                int o = __shfl_up_sync(0x000000ffu, w, off);
                if (tid >= off) w += o;
            }
            wsum[tid] = w;
        }
        __syncthreads();
        const int incl = v + (wrp ? wsum[wrp - 1] : 0);
        const int e3 = incl - h.w;
        const int e2 = e3 - h.z;
        const int e1 = e2 - h.y;
        const int e0 = e1 - h.x;
        cumE[4 * tid + 0] = e0;
        cumE[4 * tid + 1] = e1;
        cumE[4 * tid + 2] = e2;
        cumE[4 * tid + 3] = e3;
        if (tid == 255) cumE[NBUCKET] = incl;
        if (e0 < target && e1   >= target) misc[0] = 4 * tid + 0;
        if (e1 < target && e2   >= target) misc[0] = 4 * tid + 1;
        if (e2 < target && e3   >= target) misc[0] = 4 * tid + 2;
        if (e3 < target && incl >= target) misc[0] = 4 * tid + 3;
        __syncthreads();
        const int B = misc[0];
        const int total = cumE[NBUCKET];
        const int cnt = min(cumE[B + 1], cap);

        // Phase A: slot -> bucket via binary search on cumE; fetch keys
        for (int i = tid; i < cnt; i += 256) {
            int lo = 0, hi2 = B;
            while (lo < hi2) {
                int mid = (lo + hi2 + 1) >> 1;
                if (cumE[mid] <= i) lo = mid; else hi2 = mid - 1;
            }
            int b = lo, j = i - cumE[b];
            if (j < BCAP) {
                float4 r0 = bsrc[((size_t)b * BCAP + j) * 3];
                skey[i] = (((unsigned long long)__float_as_uint(r0.x)) << 32)
                          | __float_as_uint(r0.y);
                gidx[i] = b * BCAP + j;
            } else { skey[i] = ~0ull; gidx[i] = -1; }
        }
        __syncthreads();

        // Phase B: exact rank -> map[rank] = record index
        for (int i = tid; i < cnt; i += 256) {
            int gi = gidx[i];
            if (gi < 0) continue;
            unsigned long long k = skey[i];
            int b = (int)(__uint_as_float((uint32_t)(k >> 32)) * (float)NBUCKET);
            int lo = cumE[b], hiE = min(cumE[b + 1], cnt);
            int rank = lo;
            for (int j = lo; j < hiE; ++j)
                rank += (skey[j] < k);
            if (rank < target) map[rank] = gi;
        }
        __syncthreads();

        // Phase C: write output rows straight from records
        if (pool == 0) {
            np = min(total, NPOSMAX);
            for (int slot = tid; slot < np; slot += 256) {
                const float4* rp = bsrc + (size_t)map[slot] * 3;
                float4 rA = rp[0], rB = rp[1], rC = rp[2];
                float* ob = out + (size_t)(img * BATCH + slot) * 8;
                ob[0] = rA.z; ob[1] = rA.w; ob[2] = rB.x; ob[3] = rB.y;
                ob[4] = rB.z; ob[5] = rB.w; ob[6] = rC.x; ob[7] = rC.y;
                out[(size_t)NIMG * BATCH * 8 + img * BATCH + slot] = rC.z;
            }
        } else {
            const int nn = min(total, BATCH - np);
            for (int slot = np + tid; slot < np + nn; slot += 256) {
                const float4* rp = bsrc + (size_t)map[slot - np] * 3;
                float4 rA = rp[0], rB = rp[1], rC = rp[2];
                float* ob = out + (size_t)(img * BATCH + slot) * 8;
                ob[0] = rA.z; ob[1] = rA.w; ob[2] = rB.x; ob[3] = rB.y;
                ob[4] = rB.z; ob[5] = rB.w; ob[6] = rC.x; ob[7] = rC.y;
                out[(size_t)NIMG * BATCH * 8 + img * BATCH + slot] = rC.z;
            }
            for (int slot = np + nn + tid; slot < BATCH; slot += 256) {
                float* ob = out + (size_t)(img * BATCH + slot) * 8;
#pragma unroll
                for (int e = 0; e < 8; ++e) ob[e] = 0.0f;
                out[(size_t)NIMG * BATCH * 8 + img * BATCH + slot] = -1.0f;
            }
        }
    }

    __syncthreads();
    if (tid == 0) g_done[img] = 0;   // restore replay invariant
}

// ---------------------------------------------------------------------------
// Fused kernel. Blocks 0..7 = select role (one per image); blocks 8..1007 =
// match role (125 per image, 64 proposals each).
//
// Match: 8 threads per proposal-pair lane-group; thread `sub` handles GT
// subset m = sub, sub+8, ... for TWO proposals (r0, r1 = r0+32). First eval
// peeled (one exact division) so the loop invariant is best >= 0, collapsing
// division-avoidance to one test:
//   inter <= __fmul_rd(best, uni) <= best*uni  =>  rn(inter/uni) <= best
//   => strict '>' update impossible => safe to skip.  Bit-identical to ref.
// Each proposal publishes exactly ONE record into its pool's bucket array
// (bucket = floor(u*1024), slot = atomicAdd on the histogram), then the
// block releases its ticket (threadfence + atomicAdd on g_done).
// ---------------------------------------------------------------------------
__global__ __launch_bounds__(256, 6)
void fused_kernel(const float* __restrict__ gt,
                  const int*   __restrict__ gtc,
                  const float* __restrict__ pr,
                  ImgKeys keys,
                  float* __restrict__ out)
{
    extern __shared__ char sm[];

    if (blockIdx.x < NIMG) {          // select role
        select_role(blockIdx.x, out, sm);
        return;
    }

    const int mb  = blockIdx.x - NIMG;     // 0..999
    const int img = mb & 7;
    const int xb  = mb >> 3;               // 0..124
    const int tid = threadIdx.x;           // 256 threads = 32 pairs x 8 subs
    const int sub = tid & 7;
    const int pid = tid >> 3;              // 0..31
    const int base = xb * 64;
    const int r0 = base + pid;
    const int r1 = base + 32 + pid;

    float4* sgt = (float4*)sm;
    float*  sag = (float*)(sm + 4096);
    int*    sgc = (int*)(sm + 5120);

    {
        float4 g = reinterpret_cast<const float4*>(gt)[img * NGT + tid];
        sgt[tid] = g;
        sag[tid] = __fmul_rn(__fsub_rn(g.z, g.x), __fsub_rn(g.w, g.y));
        sgc[tid] = gtc[img * NGT + tid];
    }
    __syncthreads();

    float4 p0 = reinterpret_cast<const float4*>(pr)[img * NPR + r0];
    float4 p1 = reinterpret_cast<const float4*>(pr)[img * NPR + r1];
    const float ap0 = __fmul_rn(__fsub_rn(p0.z, p0.x), __fsub_rn(p0.w, p0.y));
    const float ap1 = __fmul_rn(__fsub_rn(p1.z, p1.x), __fsub_rn(p1.w, p1.y));

    float best0, best1;
    int   bi0 = sub, bi1 = sub;
    {   // peeled first eval (m = sub): unconditional exact division
        float4 g = sgt[sub];
        float ag = sag[sub];
        float wx0 = fmaxf(__fsub_rn(fminf(g.z, p0.z), fmaxf(g.x, p0.x)), 0.0f);
        float wy0 = fmaxf(__fsub_rn(fminf(g.w, p0.w), fmaxf(g.y, p0.y)), 0.0f);
        float in0 = __fmul_rn(wx0, wy0);
        best0 = __fdiv_rn(in0, __fsub_rn(__fadd_rn(ag, ap0), in0));
        float wx1 = fmaxf(__fsub_rn(fminf(g.z, p1.z), fmaxf(g.x, p1.x)), 0.0f);
        float wy1 = fmaxf(__fsub_rn(fminf(g.w, p1.w), fmaxf(g.y, p1.y)), 0.0f);
        float in1 = __fmul_rn(wx1, wy1);
        best1 = __fdiv_rn(in1, __fsub_rn(__fadd_rn(ag, ap1), in1));
    }

#pragma unroll 31
    for (int i = 1; i < NGT / 8; ++i) {
        const int m = sub + 8 * i;
        float4 g = sgt[m];
        float ag = sag[m];

        float wx0 = fmaxf(__fsub_rn(fminf(g.z, p0.z), fmaxf(g.x, p0.x)), 0.0f);
        float wy0 = fmaxf(__fsub_rn(fminf(g.w, p0.w), fmaxf(g.y, p0.y)), 0.0f);
        float in0 = __fmul_rn(wx0, wy0);
        float un0 = __fsub_rn(__fadd_rn(ag, ap0), in0);
        if (in0 > __fmul_rd(best0, un0)) {
            float iou = __fdiv_rn(in0, un0);
            if (iou > best0) { best0 = iou; bi0 = m; }
        }

        float wx1 = fmaxf(__fsub_rn(fminf(g.z, p1.z), fmaxf(g.x, p1.x)), 0.0f);
        float wy1 = fmaxf(__fsub_rn(fminf(g.w, p1.w), fmaxf(g.y, p1.y)), 0.0f);
        float in1 = __fmul_rn(wx1, wy1);
        float un1 = __fsub_rn(__fadd_rn(ag, ap1), in1);
        if (in1 > __fmul_rd(best1, un1)) {
            float iou = __fdiv_rn(in1, un1);
            if (iou > best1) { best1 = iou; bi1 = m; }
        }
    }

    // Reduce across the 8 subs: (max value, min index) == sequential first-max
#pragma unroll
    for (int off = 1; off <= 4; off <<= 1) {
        float ob = __shfl_xor_sync(0xffffffffu, best0, off);
        int  obi = __shfl_xor_sync(0xffffffffu, bi0,   off);
        if (ob > best0 || (ob == best0 && obi < bi0)) { best0 = ob; bi0 = obi; }
        ob  = __shfl_xor_sync(0xffffffffu, best1, off);
        obi = __shfl_xor_sync(0xffffffffu, bi1,   off);
        if (ob > best1 || (ob == best1 && obi < bi1)) { best1 = ob; bi1 = obi; }
    }

    const bool fg0 = (best0 >= 0.5f);      // FG_IOU == BG_IOU == 0.5
    const bool fg1 = (best1 >= 0.5f);

    // Converged Threefry (subs 4-7 duplicate subs 0-3; only subs 0-3 publish):
    //   sub&3==0: (k1, r0)  1: (k1, r1)  2: (k2, r0)  3: (k2, r1)
    const uint32_t* kv = keys.v[img];
    uint32_t kk0 = (sub & 2) ? kv[2] : kv[0];
    uint32_t kk1 = (sub & 2) ? kv[3] : kv[1];
    const int  myR  = (sub & 1) ? r1 : r0;
    const bool myFg = (sub & 1) ? fg1 : fg0;
    const int  pool = (sub & 2) >> 1;          // 0 = fg draw, 1 = bg draw
    uint32_t w0, w1;
    threefry2x32(kk0, kk1, 0u, (uint32_t)myR, w0, w1);
    float u = jax_uniform_from_bits(w0 ^ w1);

    const bool publish = (sub < 4) && (pool == 0 ? myFg : !myFg);
    if (publish) {
        int bkt = (int)(u * (float)NBUCKET);
        int hidx = (img * 2 + pool) * NBUCKET + bkt;
        int pos = atomicAdd(&g_hist[hidx], 1);
        if (pos < BCAP) {
            float4 pb = (sub & 1) ? p1 : p0;
            int    bi = (sub & 1) ? bi1 : bi0;
            float4 gb = sgt[bi];
            float  lab = (pool == 0) ? (float)sgc[bi] : 0.0f;
            float4* rp = &g_brec[((size_t)hidx * BCAP + pos) * 3];
            rp[0] = make_float4(u, __int_as_float(myR), pb.x, pb.y);
            rp[1] = make_float4(pb.z, pb.w, gb.x, gb.y);
            rp[2] = make_float4(gb.z, gb.w, lab, 0.0f);
        }
    }

    // Ticket release: all stores visible (per-thread fence), then barrier,
    // then one atomic bump of this image's done-count.
    __threadfence();
    __syncthreads();
    if (tid == 0) atomicAdd(&g_done[img], 1);
}

// ---------------------------------------------------------------------------
// Host: per-image (k1, k2) Threefry keys, partitionable mode:
//   root = key(42) = (0, 42)
//   keys[i]  = TF(root, (0, i))
//   k1, k2   = TF(keys[i], (0,0)), TF(keys[i], (0,1))
// ---------------------------------------------------------------------------
static void compute_keys(ImgKeys& out)
{
    for (int i = 0; i < NIMG; ++i) {
        uint32_t ik0, ik1;
        threefry2x32(0u, 42u, 0u, (uint32_t)i, ik0, ik1);
        uint32_t a0, a1, b0, b1;
        threefry2x32(ik0, ik1, 0u, 0u, a0, a1);   // k1
        threefry2x32(ik0, ik1, 0u, 1u, b0, b1);   // k2
        out.v[i][0] = a0; out.v[i][1] = a1;
        out.v[i][2] = b0; out.v[i][3] = b1;
    }
}

extern "C" void kernel_launch(void* const* d_in, const int* in_sizes, int n_in,
                              void* d_out, int out_size)
{
    const float* gt  = (const float*)d_in[0];  // [8,256,4]
    const int*   gtc = (const int*)  d_in[1];  // [8,256]
    const float* pr  = (const float*)d_in[2];  // [8,8000,4]
    float* out = (float*)d_out;

    (void)in_sizes; (void)n_in; (void)out_size;

    ImgKeys keys;
    compute_keys(keys);

    fused_kernel<<<NIMG + NIMG * MBLK_PER_IMG, 256, DSMEM_SZ>>>(
        gt, gtc, pr, keys, out);
}